// round 11
// baseline (speedup 1.0000x reference)
#include <cuda_runtime.h>
#include <cstdint>

// ============================================================
// BoneLinear: out = x @ (weight + w)^T
// Step 1: precompute Weff = weight + wblk@bone + bone (tf32 RNA) into g_weff
// Step 2: tf32 mma.sync GEMM [16384,4096] x [4096,4096]^T
// R11: B fragments via ldmatrix.x4 (16 LDS.32 -> 4 LDSM per ks)
// ============================================================

#define MDIM 16384
#define NDIM 4096
#define KDIM 4096

#define BM 128
#define BN 128
#define BK 32
#define STAGES 3
#define KT (KDIM / BK)        // 128
#define THREADS 128

// smem: 32 floats (128B) per row padded to 36 floats (144B) -> conflict-free
#define PITCH_F 36
#define PITCH_B (PITCH_F * 4)
#define A_STAGE_BYTES (BM * PITCH_B)   // 18432
#define B_STAGE_BYTES (BN * PITCH_B)   // 18432
#define STAGE_BYTES (A_STAGE_BYTES + B_STAGE_BYTES)  // 36864
#define SMEM_TOTAL (STAGES * STAGE_BYTES)            // 110592 (x2 CTAs = 221184)

__device__ float g_weff[(size_t)NDIM * KDIM];        // 64 MB

// ---------------- helpers ----------------
__device__ __forceinline__ uint32_t smem_u32(const void* p) {
    uint32_t a;
    asm("{ .reg .u64 t; cvta.to.shared.u64 t, %1; cvt.u32.u64 %0, t; }" : "=r"(a) : "l"(p));
    return a;
}
__device__ __forceinline__ void cp16(uint32_t sdst, const float* gsrc) {
    asm volatile("cp.async.cg.shared.global [%0], [%1], 16;" :: "r"(sdst), "l"(gsrc));
}
#define CP_COMMIT() asm volatile("cp.async.commit_group;" ::: "memory")
#define CP_WAIT1()  asm volatile("cp.async.wait_group 1;" ::: "memory")

__device__ __forceinline__ void ldmatrix4(uint32_t* r, uint32_t addr) {
    asm volatile("ldmatrix.sync.aligned.m8n8.x4.shared.b16 {%0,%1,%2,%3}, [%4];"
                 : "=r"(r[0]), "=r"(r[1]), "=r"(r[2]), "=r"(r[3]) : "r"(addr));
}
__device__ __forceinline__ void mma_tf32(float* c, const uint32_t* a, const uint32_t* b) {
    asm volatile(
        "mma.sync.aligned.m16n8k8.row.col.f32.tf32.tf32.f32 "
        "{%0,%1,%2,%3}, {%4,%5,%6,%7}, {%8,%9}, {%0,%1,%2,%3};"
        : "+f"(c[0]), "+f"(c[1]), "+f"(c[2]), "+f"(c[3])
        : "r"(a[0]), "r"(a[1]), "r"(a[2]), "r"(a[3]), "r"(b[0]), "r"(b[1]));
}

// ---------------- precompute: Weff = weight + wblk@bone + bone (tf32 RNA) ----------------
// Block (b, a): 64x64 output block. 256 threads = 16x16 grid of 4x4 micro-tiles.
#define WT_PITCH 68   // floats; 272B, 16B-aligned float4 rows, conflict-free reads
__global__ void __launch_bounds__(256, 5)
bone_weff_kernel(const float* __restrict__ weight, const float* __restrict__ bone,
                 float* __restrict__ weff) {
    __shared__ float wT[64 * WT_PITCH];   // wT[k*68+i] = Wblk[i][k]
    __shared__ float bb[64 * 64];         // bb[k*64+j] = bone[b][k][j]
    const int b = blockIdx.x, a = blockIdx.y;
    const int t = threadIdx.x;

    for (int idx = t; idx < 4096; idx += 256) {
        int i = idx >> 6, k = idx & 63;   // consecutive t -> consecutive k (gmem coalesced)
        wT[k * WT_PITCH + i] = weight[(size_t)(a * 64 + i) * KDIM + b * 64 + k];
        bb[idx] = bone[(size_t)b * 4096 + idx];
    }
    __syncthreads();

    const int ti = t >> 4;    // 0..15 -> rows i0 = ti*4
    const int tj = t & 15;    // 0..15 -> cols j0 = tj*4
    const int i0 = ti * 4, j0 = tj * 4;

    float acc[4][4];
#pragma unroll
    for (int r = 0; r < 4; r++)
#pragma unroll
        for (int cc = 0; cc < 4; cc++)
            acc[r][cc] = wT[(j0 + cc) * WT_PITCH + (i0 + r)] + bb[(i0 + r) * 64 + j0 + cc];

    const float4* wT4 = reinterpret_cast<const float4*>(wT);
    const float4* bb4 = reinterpret_cast<const float4*>(bb);
#pragma unroll 4
    for (int k = 0; k < 64; k++) {
        const float4 wv = wT4[k * (WT_PITCH / 4) + ti];  // W[i0..i0+3][k]
        const float4 bv = bb4[k * 16 + tj];              // bone[k][j0..j0+3]
        acc[0][0] += wv.x * bv.x; acc[0][1] += wv.x * bv.y; acc[0][2] += wv.x * bv.z; acc[0][3] += wv.x * bv.w;
        acc[1][0] += wv.y * bv.x; acc[1][1] += wv.y * bv.y; acc[1][2] += wv.y * bv.z; acc[1][3] += wv.y * bv.w;
        acc[2][0] += wv.z * bv.x; acc[2][1] += wv.z * bv.y; acc[2][2] += wv.z * bv.z; acc[2][3] += wv.z * bv.w;
        acc[3][0] += wv.w * bv.x; acc[3][1] += wv.w * bv.y; acc[3][2] += wv.w * bv.z; acc[3][3] += wv.w * bv.w;
    }

#pragma unroll
    for (int r = 0; r < 4; r++) {
#pragma unroll
        for (int cc = 0; cc < 4; cc++)
            asm("cvt.rna.tf32.f32 %0, %1;" : "=f"(acc[r][cc]) : "f"(acc[r][cc]));
        *reinterpret_cast<float4*>(
            weff + (size_t)(a * 64 + i0 + r) * KDIM + b * 64 + j0) =
            make_float4(acc[r][0], acc[r][1], acc[r][2], acc[r][3]);
    }
}

// ---------------- main GEMM kernel ----------------
__global__ void __launch_bounds__(THREADS, 2)
bone_gemm_kernel(const float* __restrict__ x, const float* __restrict__ weff,
                 float* __restrict__ out) {
    extern __shared__ __align__(128) char smem[];
    const uint32_t sb = smem_u32(smem);

    const int tid = threadIdx.x;
    const int wid = tid >> 5;
    const int lane = tid & 31;
    const int wm = wid & 1;        // 2 warps along M (64 rows each)
    const int wn = wid >> 1;       // 2 warps along N (64 cols each)
    const int bm = blockIdx.y * BM;
    const int bn = blockIdx.x * BN;

    // ---- cp.async: one quarter (2 A chunks + 2 B chunks per thread) ----
    auto issue_part = [&](int kt, int stage, int part) {
        const uint32_t as = sb + stage * STAGE_BYTES;
        const uint32_t bs = as + A_STAGE_BYTES;
        const int kcol = kt * BK;
#pragma unroll
        for (int j = part * 2; j < part * 2 + 2; j++) {
            int idx = tid + j * THREADS;
            int row = idx >> 3, seg = idx & 7;
            cp16(as + row * PITCH_B + seg * 16,
                 x + (size_t)(bm + row) * KDIM + kcol + seg * 4);
            cp16(bs + row * PITCH_B + seg * 16,
                 weff + (size_t)(bn + row) * KDIM + kcol + seg * 4);
        }
    };

    float c[4][8][4];
#pragma unroll
    for (int mt = 0; mt < 4; mt++)
#pragma unroll
        for (int nt = 0; nt < 8; nt++)
#pragma unroll
            for (int q = 0; q < 4; q++) c[mt][nt][q] = 0.0f;

    // per-lane smem offsets
    const uint32_t a_row = (uint32_t)(wm * 64 + (lane & 15));
    const uint32_t a_coff = (uint32_t)((lane >> 4) * 16);          // bytes within k
    // B ldmatrix lane mapping: matrices {nt,kg0},{nt,kg1},{nt+1,kg0},{nt+1,kg1}
    //   lane L: matrix m = L>>3, row j = L&7
    //   row    = wn*64 + p*16 + (m>>1)*8 + j   (p = nt pair index)
    //   byteoff= k0b + (m&1)*16
    const uint32_t b_lrow = (uint32_t)(wn * 64 + ((lane >> 4) * 8) + (lane & 7));
    const uint32_t b_loff = (uint32_t)(((lane >> 3) & 1) * 16);

    // double-buffered fragments
    uint32_t af[2][4][4];
    uint32_t bf[2][8][2];

    auto load_frags = [&](int stage, int ks, int buf) {
        const uint32_t as = sb + stage * STAGE_BYTES;
        const uint32_t bs = as + A_STAGE_BYTES;
        const uint32_t k0b = (uint32_t)(ks * 32);  // 8 floats
#pragma unroll
        for (int mt = 0; mt < 4; mt++)
            ldmatrix4(af[buf][mt], as + (a_row + mt * 16) * PITCH_B + k0b + a_coff);
#pragma unroll
        for (int p = 0; p < 4; p++) {
            uint32_t r[4];
            ldmatrix4(r, bs + (b_lrow + p * 16) * PITCH_B + k0b + b_loff);
            bf[buf][2 * p][0] = r[0];
            bf[buf][2 * p][1] = r[1];
            bf[buf][2 * p + 1][0] = r[2];
            bf[buf][2 * p + 1][1] = r[3];
        }
    };

    // ---- prologue: stage0 full, stage1 full, stage2 part0 ----
#pragma unroll
    for (int p = 0; p < 4; p++) issue_part(0, 0, p);
    CP_COMMIT();
#pragma unroll
    for (int p = 0; p < 4; p++) issue_part(1, 1, p);
    CP_COMMIT();
    issue_part(2, 2, 0);

    CP_WAIT1();          // stage0 group complete
    __syncthreads();
    load_frags(0, 0, 0); // frag0 of kt=0 into buf0

    // ---- mainloop ----
#pragma unroll 1
    for (int kt = 0; kt < KT; kt++) {
        const int f2 = (kt + 2) % STAGES;    // stage being refilled by parts 1-3
        const int f3 = (kt + 3) % STAGES;    // stage refill started at ks3
        const int cstage = kt % STAGES;
        const bool issue23 = (kt + 2) < KT;
        const bool issue3  = (kt + 3) < KT;

        // ks0
        load_frags(cstage, 1, 1);
#pragma unroll
        for (int mt = 0; mt < 4; mt++)
#pragma unroll
            for (int nt = 0; nt < 8; nt++) mma_tf32(c[mt][nt], af[0][mt], bf[0][nt]);
        if (issue23) issue_part(kt + 2, f2, 1);

        // ks1
        load_frags(cstage, 2, 0);
#pragma unroll
        for (int mt = 0; mt < 4; mt++)
#pragma unroll
            for (int nt = 0; nt < 8; nt++) mma_tf32(c[mt][nt], af[1][mt], bf[1][nt]);
        if (issue23) issue_part(kt + 2, f2, 2);

        // ks2 (last smem read of cstage is this frag load)
        load_frags(cstage, 3, 1);
#pragma unroll
        for (int mt = 0; mt < 4; mt++)
#pragma unroll
            for (int nt = 0; nt < 8; nt++) mma_tf32(c[mt][nt], af[0][mt], bf[0][nt]);
        if (issue23) issue_part(kt + 2, f2, 3);
        CP_COMMIT();
        CP_WAIT1();
        __syncthreads();

        // ks3 (overlap next-stage frag0 + refill part0 with this mma block)
        if (kt + 1 < KT) load_frags((kt + 1) % STAGES, 0, 0);
#pragma unroll
        for (int mt = 0; mt < 4; mt++)
#pragma unroll
            for (int nt = 0; nt < 8; nt++) mma_tf32(c[mt][nt], af[1][mt], bf[1][nt]);
        if (issue3) issue_part(kt + 3, f3, 0);
    }

    // ---- epilogue: fp32 stores ----
    const int er = bm + wm * 64 + (lane >> 2);
    const int ec = bn + wn * 64 + 2 * (lane & 3);
#pragma unroll
    for (int mt = 0; mt < 4; mt++) {
#pragma unroll
        for (int nt = 0; nt < 8; nt++) {
            float* p0 = out + (size_t)(er + mt * 16) * NDIM + ec + nt * 8;
            float* p1 = p0 + 8 * NDIM;
            *reinterpret_cast<float2*>(p0) = make_float2(c[mt][nt][0], c[mt][nt][1]);
            *reinterpret_cast<float2*>(p1) = make_float2(c[mt][nt][2], c[mt][nt][3]);
        }
    }
}

// ---------------- host ----------------
extern "C" void kernel_launch(void* const* d_in, const int* in_sizes, int n_in,
                              void* d_out, int out_size) {
    (void)in_sizes; (void)n_in; (void)out_size;
    const float* x      = (const float*)d_in[0];
    const float* weight = (const float*)d_in[1];
    const float* bone   = (const float*)d_in[2];
    float* out          = (float*)d_out;

    void* weff_ptr = nullptr;
    cudaGetSymbolAddress(&weff_ptr, g_weff);

    cudaFuncSetAttribute((const void*)bone_gemm_kernel,
                         cudaFuncAttributeMaxDynamicSharedMemorySize, SMEM_TOTAL);

    bone_weff_kernel<<<dim3(64, 64), 256>>>(weight, bone, (float*)weff_ptr);
    bone_gemm_kernel<<<dim3(NDIM / BN, MDIM / BM), THREADS, SMEM_TOTAL>>>(
        x, (const float*)weff_ptr, out);
}

// round 12
// speedup vs baseline: 1.6437x; 1.6437x over previous
#include <cuda_runtime.h>
#include <cstdint>

// ============================================================
// BoneLinear: out = x @ (weight + w)^T
// Step 1: precompute Weff = weight + wblk@bone + bone (tf32 RNA) into g_weff
// Step 2: tf32 mma.sync GEMM [16384,4096] x [4096,4096]^T
// R12: R10 pipeline (scalar-LDS B feed, proven) + kt-loop unrolled by 3
//      so all stage indices / smem bases are compile-time constants
// ============================================================

#define MDIM 16384
#define NDIM 4096
#define KDIM 4096

#define BM 128
#define BN 128
#define BK 32
#define STAGES 3
#define KT (KDIM / BK)        // 128
#define THREADS 128

// smem: 32 floats (128B) per row padded to 36 floats (144B) -> conflict-free
#define PITCH_F 36
#define PITCH_B (PITCH_F * 4)
#define A_STAGE_BYTES (BM * PITCH_B)   // 18432
#define B_STAGE_BYTES (BN * PITCH_B)   // 18432
#define STAGE_BYTES (A_STAGE_BYTES + B_STAGE_BYTES)  // 36864
#define SMEM_TOTAL (STAGES * STAGE_BYTES)            // 110592 (x2 CTAs = 221184)

__device__ float g_weff[(size_t)NDIM * KDIM];        // 64 MB

// ---------------- helpers ----------------
__device__ __forceinline__ uint32_t smem_u32(const void* p) {
    uint32_t a;
    asm("{ .reg .u64 t; cvta.to.shared.u64 t, %1; cvt.u32.u64 %0, t; }" : "=r"(a) : "l"(p));
    return a;
}
__device__ __forceinline__ void cp16(uint32_t sdst, const float* gsrc) {
    asm volatile("cp.async.cg.shared.global [%0], [%1], 16;" :: "r"(sdst), "l"(gsrc));
}
#define CP_COMMIT() asm volatile("cp.async.commit_group;" ::: "memory")
#define CP_WAIT1()  asm volatile("cp.async.wait_group 1;" ::: "memory")

__device__ __forceinline__ void ldmatrix4(uint32_t* r, uint32_t addr) {
    asm volatile("ldmatrix.sync.aligned.m8n8.x4.shared.b16 {%0,%1,%2,%3}, [%4];"
                 : "=r"(r[0]), "=r"(r[1]), "=r"(r[2]), "=r"(r[3]) : "r"(addr));
}
__device__ __forceinline__ uint32_t lds_b32(uint32_t addr) {
    uint32_t v;
    asm volatile("ld.shared.b32 %0, [%1];" : "=r"(v) : "r"(addr));
    return v;
}
__device__ __forceinline__ void mma_tf32(float* c, const uint32_t* a, const uint32_t* b) {
    asm volatile(
        "mma.sync.aligned.m16n8k8.row.col.f32.tf32.tf32.f32 "
        "{%0,%1,%2,%3}, {%4,%5,%6,%7}, {%8,%9}, {%0,%1,%2,%3};"
        : "+f"(c[0]), "+f"(c[1]), "+f"(c[2]), "+f"(c[3])
        : "r"(a[0]), "r"(a[1]), "r"(a[2]), "r"(a[3]), "r"(b[0]), "r"(b[1]));
}

// ---------------- precompute: Weff = weight + wblk@bone + bone (tf32 RNA) ----------------
// Block (b, a): 64x64 output block. 256 threads = 16x16 grid of 4x4 micro-tiles.
#define WT_PITCH 68   // floats; 272B, 16B-aligned float4 rows, conflict-free reads
__global__ void __launch_bounds__(256, 5)
bone_weff_kernel(const float* __restrict__ weight, const float* __restrict__ bone,
                 float* __restrict__ weff) {
    __shared__ float wT[64 * WT_PITCH];   // wT[k*68+i] = Wblk[i][k]
    __shared__ float bb[64 * 64];         // bb[k*64+j] = bone[b][k][j]
    const int b = blockIdx.x, a = blockIdx.y;
    const int t = threadIdx.x;

    for (int idx = t; idx < 4096; idx += 256) {
        int i = idx >> 6, k = idx & 63;   // consecutive t -> consecutive k (gmem coalesced)
        wT[k * WT_PITCH + i] = weight[(size_t)(a * 64 + i) * KDIM + b * 64 + k];
        bb[idx] = bone[(size_t)b * 4096 + idx];
    }
    __syncthreads();

    const int ti = t >> 4;    // 0..15 -> rows i0 = ti*4
    const int tj = t & 15;    // 0..15 -> cols j0 = tj*4
    const int i0 = ti * 4, j0 = tj * 4;

    float acc[4][4];
#pragma unroll
    for (int r = 0; r < 4; r++)
#pragma unroll
        for (int cc = 0; cc < 4; cc++)
            acc[r][cc] = wT[(j0 + cc) * WT_PITCH + (i0 + r)] + bb[(i0 + r) * 64 + j0 + cc];

    const float4* wT4 = reinterpret_cast<const float4*>(wT);
    const float4* bb4 = reinterpret_cast<const float4*>(bb);
#pragma unroll 4
    for (int k = 0; k < 64; k++) {
        const float4 wv = wT4[k * (WT_PITCH / 4) + ti];  // W[i0..i0+3][k]
        const float4 bv = bb4[k * 16 + tj];              // bone[k][j0..j0+3]
        acc[0][0] += wv.x * bv.x; acc[0][1] += wv.x * bv.y; acc[0][2] += wv.x * bv.z; acc[0][3] += wv.x * bv.w;
        acc[1][0] += wv.y * bv.x; acc[1][1] += wv.y * bv.y; acc[1][2] += wv.y * bv.z; acc[1][3] += wv.y * bv.w;
        acc[2][0] += wv.z * bv.x; acc[2][1] += wv.z * bv.y; acc[2][2] += wv.z * bv.z; acc[2][3] += wv.z * bv.w;
        acc[3][0] += wv.w * bv.x; acc[3][1] += wv.w * bv.y; acc[3][2] += wv.w * bv.z; acc[3][3] += wv.w * bv.w;
    }

#pragma unroll
    for (int r = 0; r < 4; r++) {
#pragma unroll
        for (int cc = 0; cc < 4; cc++)
            asm("cvt.rna.tf32.f32 %0, %1;" : "=f"(acc[r][cc]) : "f"(acc[r][cc]));
        *reinterpret_cast<float4*>(
            weff + (size_t)(a * 64 + i0 + r) * KDIM + b * 64 + j0) =
            make_float4(acc[r][0], acc[r][1], acc[r][2], acc[r][3]);
    }
}

// ---------------- main GEMM kernel ----------------
__global__ void __launch_bounds__(THREADS, 2)
bone_gemm_kernel(const float* __restrict__ x, const float* __restrict__ weff,
                 float* __restrict__ out) {
    extern __shared__ __align__(128) char smem[];
    const uint32_t sb = smem_u32(smem);

    const int tid = threadIdx.x;
    const int wid = tid >> 5;
    const int lane = tid & 31;
    const int wm = wid & 1;        // 2 warps along M (64 rows each)
    const int wn = wid >> 1;       // 2 warps along N (64 cols each)
    const int bm = blockIdx.y * BM;
    const int bn = blockIdx.x * BN;

    // ---- cp.async: one quarter (2 A chunks + 2 B chunks per thread) ----
    auto issue_part = [&](int kt, int stage, int part) {
        const uint32_t as = sb + stage * STAGE_BYTES;
        const uint32_t bs = as + A_STAGE_BYTES;
        const int kcol = kt * BK;
#pragma unroll
        for (int j = part * 2; j < part * 2 + 2; j++) {
            int idx = tid + j * THREADS;
            int row = idx >> 3, seg = idx & 7;
            cp16(as + row * PITCH_B + seg * 16,
                 x + (size_t)(bm + row) * KDIM + kcol + seg * 4);
            cp16(bs + row * PITCH_B + seg * 16,
                 weff + (size_t)(bn + row) * KDIM + kcol + seg * 4);
        }
    };

    float c[4][8][4];
#pragma unroll
    for (int mt = 0; mt < 4; mt++)
#pragma unroll
        for (int nt = 0; nt < 8; nt++)
#pragma unroll
            for (int q = 0; q < 4; q++) c[mt][nt][q] = 0.0f;

    // per-lane smem offsets
    const uint32_t a_row = (uint32_t)(wm * 64 + (lane & 15));
    const uint32_t a_coff = (uint32_t)((lane >> 4) * 16);          // bytes within k
    const uint32_t b_row = (uint32_t)(wn * 64 + (lane >> 2));      // + nt*8
    const uint32_t b_koff = (uint32_t)((lane & 3) * 4);            // bytes

    // double-buffered fragments
    uint32_t af[2][4][4];
    uint32_t bf[2][8][2];

    auto load_frags = [&](int stage, int ks, int buf) {
        const uint32_t as = sb + stage * STAGE_BYTES;
        const uint32_t bs = as + A_STAGE_BYTES;
        const uint32_t k0b = (uint32_t)(ks * 32);  // 8 floats
#pragma unroll
        for (int mt = 0; mt < 4; mt++)
            ldmatrix4(af[buf][mt], as + (a_row + mt * 16) * PITCH_B + k0b + a_coff);
#pragma unroll
        for (int nt = 0; nt < 8; nt++) {
            uint32_t ba = bs + (b_row + nt * 8) * PITCH_B + k0b + b_koff;
            bf[buf][nt][0] = lds_b32(ba);
            bf[buf][nt][1] = lds_b32(ba + 16);
        }
    };

#define MMAS(B)                                                                    \
    do {                                                                           \
        _Pragma("unroll")                                                          \
        for (int mt = 0; mt < 4; mt++)                                             \
            _Pragma("unroll")                                                      \
            for (int nt = 0; nt < 8; nt++)                                         \
                mma_tf32(c[mt][nt], af[B][mt], bf[B][nt]);                         \
    } while (0)

    // one kt iteration; CS/NS/F2/F3 are compile-time stage constants
#define KT_BODY(KTV, CS, NS, F2, F3)                                               \
    do {                                                                           \
        const int _kt = (KTV);                                                     \
        const bool i23 = _kt + 2 < KT;                                             \
        const bool i3  = _kt + 3 < KT;                                             \
        load_frags(CS, 1, 1);                                                      \
        MMAS(0);                                                                   \
        if (i23) issue_part(_kt + 2, F2, 1);                                       \
        load_frags(CS, 2, 0);                                                      \
        MMAS(1);                                                                   \
        if (i23) issue_part(_kt + 2, F2, 2);                                       \
        load_frags(CS, 3, 1);                                                      \
        MMAS(0);                                                                   \
        if (i23) issue_part(_kt + 2, F2, 3);                                       \
        CP_COMMIT();                                                               \
        CP_WAIT1();                                                                \
        __syncthreads();                                                           \
        if (_kt + 1 < KT) load_frags(NS, 0, 0);                                    \
        MMAS(1);                                                                   \
        if (i3) issue_part(_kt + 3, F3, 0);                                        \
    } while (0)

    // ---- prologue: stage0 full, stage1 full, stage2 part0 ----
#pragma unroll
    for (int p = 0; p < 4; p++) issue_part(0, 0, p);
    CP_COMMIT();
#pragma unroll
    for (int p = 0; p < 4; p++) issue_part(1, 1, p);
    CP_COMMIT();
    issue_part(2, 2, 0);

    CP_WAIT1();          // stage0 group complete
    __syncthreads();
    load_frags(0, 0, 0); // frag0 of kt=0 into buf0

    // ---- mainloop: 42 triples (kt = 0..125), stages compile-time ----
#pragma unroll 1
    for (int kt = 0; kt < 126; kt += 3) {
        KT_BODY(kt,     0, 1, 2, 0);
        KT_BODY(kt + 1, 1, 2, 0, 1);
        KT_BODY(kt + 2, 2, 0, 1, 2);
    }
    // tail: kt = 126 (stage 0), kt = 127 (stage 1)
    KT_BODY(126, 0, 1, 2, 0);
    KT_BODY(127, 1, 2, 0, 1);

#undef KT_BODY
#undef MMAS

    // ---- epilogue: fp32 stores ----
    const int er = bm + wm * 64 + (lane >> 2);
    const int ec = bn + wn * 64 + 2 * (lane & 3);
#pragma unroll
    for (int mt = 0; mt < 4; mt++) {
#pragma unroll
        for (int nt = 0; nt < 8; nt++) {
            float* p0 = out + (size_t)(er + mt * 16) * NDIM + ec + nt * 8;
            float* p1 = p0 + 8 * NDIM;
            *reinterpret_cast<float2*>(p0) = make_float2(c[mt][nt][0], c[mt][nt][1]);
            *reinterpret_cast<float2*>(p1) = make_float2(c[mt][nt][2], c[mt][nt][3]);
        }
    }
}

// ---------------- host ----------------
extern "C" void kernel_launch(void* const* d_in, const int* in_sizes, int n_in,
                              void* d_out, int out_size) {
    (void)in_sizes; (void)n_in; (void)out_size;
    const float* x      = (const float*)d_in[0];
    const float* weight = (const float*)d_in[1];
    const float* bone   = (const float*)d_in[2];
    float* out          = (float*)d_out;

    void* weff_ptr = nullptr;
    cudaGetSymbolAddress(&weff_ptr, g_weff);

    cudaFuncSetAttribute((const void*)bone_gemm_kernel,
                         cudaFuncAttributeMaxDynamicSharedMemorySize, SMEM_TOTAL);

    bone_weff_kernel<<<dim3(64, 64), 256>>>(weight, bone, (float*)weff_ptr);
    bone_gemm_kernel<<<dim3(NDIM / BN, MDIM / BM), THREADS, SMEM_TOTAL>>>(
        x, (const float*)weff_ptr, out);
}

// round 13
// speedup vs baseline: 1.6613x; 1.0107x over previous
#include <cuda_runtime.h>
#include <cstdint>

// ============================================================
// BoneLinear: out = x @ (weight + w)^T
// Step 1: Weff = weight + wblk@bone + bone (tf32 RNA) into g_weff
//         R13: weff block-product on the TENSOR pipe (tf32 mma.sync),
//              epilogue adds weight+bone elementwise. GEMM frozen from R12.
// Step 2: tf32 mma.sync GEMM [16384,4096] x [4096,4096]^T
// ============================================================

#define MDIM 16384
#define NDIM 4096
#define KDIM 4096

#define BM 128
#define BN 128
#define BK 32
#define STAGES 3
#define KT (KDIM / BK)        // 128
#define THREADS 128

// smem: 32 floats (128B) per row padded to 36 floats (144B) -> conflict-free
#define PITCH_F 36
#define PITCH_B (PITCH_F * 4)
#define A_STAGE_BYTES (BM * PITCH_B)   // 18432
#define B_STAGE_BYTES (BN * PITCH_B)   // 18432
#define STAGE_BYTES (A_STAGE_BYTES + B_STAGE_BYTES)  // 36864
#define SMEM_TOTAL (STAGES * STAGE_BYTES)            // 110592 (x2 CTAs = 221184)

__device__ float g_weff[(size_t)NDIM * KDIM];        // 64 MB

// ---------------- helpers ----------------
__device__ __forceinline__ uint32_t smem_u32(const void* p) {
    uint32_t a;
    asm("{ .reg .u64 t; cvta.to.shared.u64 t, %1; cvt.u32.u64 %0, t; }" : "=r"(a) : "l"(p));
    return a;
}
__device__ __forceinline__ void cp16(uint32_t sdst, const float* gsrc) {
    asm volatile("cp.async.cg.shared.global [%0], [%1], 16;" :: "r"(sdst), "l"(gsrc));
}
#define CP_COMMIT() asm volatile("cp.async.commit_group;" ::: "memory")
#define CP_WAIT1()  asm volatile("cp.async.wait_group 1;" ::: "memory")

__device__ __forceinline__ void ldmatrix4(uint32_t* r, uint32_t addr) {
    asm volatile("ldmatrix.sync.aligned.m8n8.x4.shared.b16 {%0,%1,%2,%3}, [%4];"
                 : "=r"(r[0]), "=r"(r[1]), "=r"(r[2]), "=r"(r[3]) : "r"(addr));
}
__device__ __forceinline__ uint32_t lds_b32(uint32_t addr) {
    uint32_t v;
    asm volatile("ld.shared.b32 %0, [%1];" : "=r"(v) : "r"(addr));
    return v;
}
__device__ __forceinline__ void mma_tf32(float* c, const uint32_t* a, const uint32_t* b) {
    asm volatile(
        "mma.sync.aligned.m16n8k8.row.col.f32.tf32.tf32.f32 "
        "{%0,%1,%2,%3}, {%4,%5,%6,%7}, {%8,%9}, {%0,%1,%2,%3};"
        : "+f"(c[0]), "+f"(c[1]), "+f"(c[2]), "+f"(c[3])
        : "r"(a[0]), "r"(a[1]), "r"(a[2]), "r"(a[3]), "r"(b[0]), "r"(b[1]));
}

// ---------------- precompute: Weff = weight + wblk@bone + bone, on tensor pipe ----------------
// Block (b, a): wblk[64,64] @ bone[b][64,64] via tf32 mma; epilogue adds weight+bone.
// Fragment addressing copied verbatim from the proven main-GEMM patterns.
#define WP 68   // pitch floats = 272B; 272 mod 128 == 144 mod 128 (proven bank class)
__global__ void __launch_bounds__(128, 6)
bone_weff_kernel(const float* __restrict__ weight, const float* __restrict__ bone,
                 float* __restrict__ weff) {
    __shared__ float wS[64 * WP];   // wS[i*WP + k] = wblk[i][k]   (A, row-major)
    __shared__ float bT[64 * WP];   // bT[j*WP + k] = bone[b][k][j] (B, col-major for row.col)
    const int b = blockIdx.x, a = blockIdx.y;
    const int t = threadIdx.x;
    const int wid = t >> 5, lane = t & 31;

    // fill A: coalesced float4 along k
    for (int idx = t; idx < 1024; idx += 128) {
        int i = idx >> 4, k4 = idx & 15;
        float4 v = *reinterpret_cast<const float4*>(
            weight + (size_t)(a * 64 + i) * KDIM + b * 64 + k4 * 4);
        *reinterpret_cast<float4*>(wS + i * WP + k4 * 4) = v;
    }
    // fill B^T: read bone coalesced along j, scatter-store (fill-only conflicts, cheap)
    for (int idx = t; idx < 4096; idx += 128) {
        int k = idx >> 6, j = idx & 63;
        bT[j * WP + k] = bone[(size_t)b * 4096 + k * 64 + j];
    }
    __syncthreads();

    // warp wid handles m-rows wid*16..wid*16+15, all 64 n, k=64 (8 ksteps)
    float c[8][4];
#pragma unroll
    for (int nt = 0; nt < 8; nt++)
#pragma unroll
        for (int q = 0; q < 4; q++) c[nt][q] = 0.0f;

    const uint32_t sbw = smem_u32(wS);
    const uint32_t sbb = smem_u32(bT);
    const uint32_t a_addr = sbw + (uint32_t)(wid * 16 + (lane & 15)) * (WP * 4)
                                + (uint32_t)((lane >> 4) * 16);
    const uint32_t b_row = (uint32_t)(lane >> 2);
    const uint32_t b_koff = (uint32_t)((lane & 3) * 4);

#pragma unroll
    for (int ks = 0; ks < 8; ks++) {
        uint32_t af[4];
        ldmatrix4(af, a_addr + ks * 32);
#pragma unroll
        for (int nt = 0; nt < 8; nt++) {
            uint32_t bfr[2];
            uint32_t ba = sbb + (b_row + nt * 8) * (WP * 4) + (uint32_t)(ks * 32) + b_koff;
            bfr[0] = lds_b32(ba);
            bfr[1] = lds_b32(ba + 16);
            mma_tf32(c[nt], af, bfr);
        }
    }

    // epilogue: weff = cvt.rna(c + weight + bone)
    const int er = wid * 16 + (lane >> 2);
    const int ec = 2 * (lane & 3);
#pragma unroll
    for (int nt = 0; nt < 8; nt++) {
#pragma unroll
        for (int h = 0; h < 2; h++) {
            const int i = er + h * 8;
            const int j = ec + nt * 8;
            const size_t go = (size_t)(a * 64 + i) * KDIM + b * 64 + j;
            const float2 wv = *reinterpret_cast<const float2*>(weight + go);
            const float2 bv = *reinterpret_cast<const float2*>(
                bone + (size_t)b * 4096 + i * 64 + j);
            float r0 = c[nt][h * 2 + 0] + wv.x + bv.x;
            float r1 = c[nt][h * 2 + 1] + wv.y + bv.y;
            asm("cvt.rna.tf32.f32 %0, %1;" : "=f"(r0) : "f"(r0));
            asm("cvt.rna.tf32.f32 %0, %1;" : "=f"(r1) : "f"(r1));
            *reinterpret_cast<float2*>(weff + go) = make_float2(r0, r1);
        }
    }
}

// ---------------- main GEMM kernel (frozen from R12) ----------------
__global__ void __launch_bounds__(THREADS, 2)
bone_gemm_kernel(const float* __restrict__ x, const float* __restrict__ weff,
                 float* __restrict__ out) {
    extern __shared__ __align__(128) char smem[];
    const uint32_t sb = smem_u32(smem);

    const int tid = threadIdx.x;
    const int wid = tid >> 5;
    const int lane = tid & 31;
    const int wm = wid & 1;        // 2 warps along M (64 rows each)
    const int wn = wid >> 1;       // 2 warps along N (64 cols each)
    const int bm = blockIdx.y * BM;
    const int bn = blockIdx.x * BN;

    // ---- cp.async: one quarter (2 A chunks + 2 B chunks per thread) ----
    auto issue_part = [&](int kt, int stage, int part) {
        const uint32_t as = sb + stage * STAGE_BYTES;
        const uint32_t bs = as + A_STAGE_BYTES;
        const int kcol = kt * BK;
#pragma unroll
        for (int j = part * 2; j < part * 2 + 2; j++) {
            int idx = tid + j * THREADS;
            int row = idx >> 3, seg = idx & 7;
            cp16(as + row * PITCH_B + seg * 16,
                 x + (size_t)(bm + row) * KDIM + kcol + seg * 4);
            cp16(bs + row * PITCH_B + seg * 16,
                 weff + (size_t)(bn + row) * KDIM + kcol + seg * 4);
        }
    };

    float c[4][8][4];
#pragma unroll
    for (int mt = 0; mt < 4; mt++)
#pragma unroll
        for (int nt = 0; nt < 8; nt++)
#pragma unroll
            for (int q = 0; q < 4; q++) c[mt][nt][q] = 0.0f;

    // per-lane smem offsets
    const uint32_t a_row = (uint32_t)(wm * 64 + (lane & 15));
    const uint32_t a_coff = (uint32_t)((lane >> 4) * 16);          // bytes within k
    const uint32_t b_row = (uint32_t)(wn * 64 + (lane >> 2));      // + nt*8
    const uint32_t b_koff = (uint32_t)((lane & 3) * 4);            // bytes

    // double-buffered fragments
    uint32_t af[2][4][4];
    uint32_t bf[2][8][2];

    auto load_frags = [&](int stage, int ks, int buf) {
        const uint32_t as = sb + stage * STAGE_BYTES;
        const uint32_t bs = as + A_STAGE_BYTES;
        const uint32_t k0b = (uint32_t)(ks * 32);  // 8 floats
#pragma unroll
        for (int mt = 0; mt < 4; mt++)
            ldmatrix4(af[buf][mt], as + (a_row + mt * 16) * PITCH_B + k0b + a_coff);
#pragma unroll
        for (int nt = 0; nt < 8; nt++) {
            uint32_t ba = bs + (b_row + nt * 8) * PITCH_B + k0b + b_koff;
            bf[buf][nt][0] = lds_b32(ba);
            bf[buf][nt][1] = lds_b32(ba + 16);
        }
    };

#define MMAS(B)                                                                    \
    do {                                                                           \
        _Pragma("unroll")                                                          \
        for (int mt = 0; mt < 4; mt++)                                             \
            _Pragma("unroll")                                                      \
            for (int nt = 0; nt < 8; nt++)                                         \
                mma_tf32(c[mt][nt], af[B][mt], bf[B][nt]);                         \
    } while (0)

    // one kt iteration; CS/NS/F2/F3 are compile-time stage constants
#define KT_BODY(KTV, CS, NS, F2, F3)                                               \
    do {                                                                           \
        const int _kt = (KTV);                                                     \
        const bool i23 = _kt + 2 < KT;                                             \
        const bool i3  = _kt + 3 < KT;                                             \
        load_frags(CS, 1, 1);                                                      \
        MMAS(0);                                                                   \
        if (i23) issue_part(_kt + 2, F2, 1);                                       \
        load_frags(CS, 2, 0);                                                      \
        MMAS(1);                                                                   \
        if (i23) issue_part(_kt + 2, F2, 2);                                       \
        load_frags(CS, 3, 1);                                                      \
        MMAS(0);                                                                   \
        if (i23) issue_part(_kt + 2, F2, 3);                                       \
        CP_COMMIT();                                                               \
        CP_WAIT1();                                                                \
        __syncthreads();                                                           \
        if (_kt + 1 < KT) load_frags(NS, 0, 0);                                    \
        MMAS(1);                                                                   \
        if (i3) issue_part(_kt + 3, F3, 0);                                        \
    } while (0)

    // ---- prologue: stage0 full, stage1 full, stage2 part0 ----
#pragma unroll
    for (int p = 0; p < 4; p++) issue_part(0, 0, p);
    CP_COMMIT();
#pragma unroll
    for (int p = 0; p < 4; p++) issue_part(1, 1, p);
    CP_COMMIT();
    issue_part(2, 2, 0);

    CP_WAIT1();          // stage0 group complete
    __syncthreads();
    load_frags(0, 0, 0); // frag0 of kt=0 into buf0

    // ---- mainloop: 42 triples (kt = 0..125), stages compile-time ----
#pragma unroll 1
    for (int kt = 0; kt < 126; kt += 3) {
        KT_BODY(kt,     0, 1, 2, 0);
        KT_BODY(kt + 1, 1, 2, 0, 1);
        KT_BODY(kt + 2, 2, 0, 1, 2);
    }
    // tail: kt = 126 (stage 0), kt = 127 (stage 1)
    KT_BODY(126, 0, 1, 2, 0);
    KT_BODY(127, 1, 2, 0, 1);

#undef KT_BODY
#undef MMAS

    // ---- epilogue: fp32 stores ----
    const int er = bm + wm * 64 + (lane >> 2);
    const int ec = bn + wn * 64 + 2 * (lane & 3);
#pragma unroll
    for (int mt = 0; mt < 4; mt++) {
#pragma unroll
        for (int nt = 0; nt < 8; nt++) {
            float* p0 = out + (size_t)(er + mt * 16) * NDIM + ec + nt * 8;
            float* p1 = p0 + 8 * NDIM;
            *reinterpret_cast<float2*>(p0) = make_float2(c[mt][nt][0], c[mt][nt][1]);
            *reinterpret_cast<float2*>(p1) = make_float2(c[mt][nt][2], c[mt][nt][3]);
        }
    }
}

// ---------------- host ----------------
extern "C" void kernel_launch(void* const* d_in, const int* in_sizes, int n_in,
                              void* d_out, int out_size) {
    (void)in_sizes; (void)n_in; (void)out_size;
    const float* x      = (const float*)d_in[0];
    const float* weight = (const float*)d_in[1];
    const float* bone   = (const float*)d_in[2];
    float* out          = (float*)d_out;

    void* weff_ptr = nullptr;
    cudaGetSymbolAddress(&weff_ptr, g_weff);

    cudaFuncSetAttribute((const void*)bone_gemm_kernel,
                         cudaFuncAttributeMaxDynamicSharedMemorySize, SMEM_TOTAL);

    bone_weff_kernel<<<dim3(64, 64), 128>>>(weight, bone, (float*)weff_ptr);
    bone_gemm_kernel<<<dim3(NDIM / BN, MDIM / BM), THREADS, SMEM_TOTAL>>>(
        x, (const float*)weff_ptr, out);
}